// round 3
// baseline (speedup 1.0000x reference)
#include <cuda_runtime.h>
#include <math.h>

#define DIM 256
#define NHEAD 8
#define HD 32
#define BATCH 2
#define ND 2048
#define NOC 2048
#define ROWS (BATCH*ND)          // 4096
#define EPSF 1e-5f
#define LAMBDA_INIT 0.1f
#define SCALEF 0.17677669529663687f   // 32^-0.5

// ---------------- scratch (static __device__, no allocations) ----------------
__device__ float g_x[ROWS*DIM];        // LN1(drift)
__device__ float g_Q[ROWS*2*DIM];      // x @ Wq^T   [4096,512]
__device__ float g_K[ROWS*2*DIM];      // ocean @ Wk^T
__device__ float g_V[ROWS*DIM];        // ocean @ Wv^T
__device__ float g_attn[ROWS*DIM];     // attention output (head-major cols)
__device__ float g_d2[ROWS*DIM];       // drift + attn@Wo^T
__device__ float g_y[ROWS*DIM];        // LN2
__device__ float g_h[ROWS*4*DIM];      // gelu(fc1)
__device__ float g_lam[NHEAD];

// ---------------- LayerNorm: one warp per 256-elem row ----------------
__global__ __launch_bounds__(256) void ln_kernel(const float* __restrict__ in,
                                                 const float* __restrict__ gamma,
                                                 const float* __restrict__ beta,
                                                 float* __restrict__ out) {
    int warp = threadIdx.x >> 5, lane = threadIdx.x & 31;
    size_t row = (size_t)blockIdx.x * 8 + warp;
    const float* p = in + row * DIM;
    float4 a = *(const float4*)(p + lane * 4);
    float4 b = *(const float4*)(p + 128 + lane * 4);
    float s  = a.x + a.y + a.z + a.w + b.x + b.y + b.z + b.w;
    float ss = a.x*a.x + a.y*a.y + a.z*a.z + a.w*a.w
             + b.x*b.x + b.y*b.y + b.z*b.z + b.w*b.w;
    #pragma unroll
    for (int m = 16; m; m >>= 1) {
        s  += __shfl_xor_sync(0xffffffffu, s,  m);
        ss += __shfl_xor_sync(0xffffffffu, ss, m);
    }
    float mean = s * (1.0f / DIM);
    float var  = ss * (1.0f / DIM) - mean * mean;
    float rinv = rsqrtf(var + EPSF);
    float4 g1 = *(const float4*)(gamma + lane * 4);
    float4 g2 = *(const float4*)(gamma + 128 + lane * 4);
    float4 b1 = *(const float4*)(beta + lane * 4);
    float4 b2 = *(const float4*)(beta + 128 + lane * 4);
    float4 o1, o2;
    o1.x = (a.x - mean) * rinv * g1.x + b1.x;
    o1.y = (a.y - mean) * rinv * g1.y + b1.y;
    o1.z = (a.z - mean) * rinv * g1.z + b1.z;
    o1.w = (a.w - mean) * rinv * g1.w + b1.w;
    o2.x = (b.x - mean) * rinv * g2.x + b2.x;
    o2.y = (b.y - mean) * rinv * g2.y + b2.y;
    o2.z = (b.z - mean) * rinv * g2.z + b2.z;
    o2.w = (b.w - mean) * rinv * g2.w + b2.w;
    *(float4*)(out + row * DIM + lane * 4) = o1;
    *(float4*)(out + row * DIM + 128 + lane * 4) = o2;
}

// ---------------- lambda per head ----------------
__global__ void lam_kernel(const float* __restrict__ lq1, const float* __restrict__ lk1,
                           const float* __restrict__ lq2, const float* __restrict__ lk2) {
    int h = threadIdx.x >> 5, lane = threadIdx.x & 31;
    float a = lq1[h * HD + lane] * lk1[h * HD + lane];
    float b = lq2[h * HD + lane] * lk2[h * HD + lane];
    #pragma unroll
    for (int m = 16; m; m >>= 1) {
        a += __shfl_xor_sync(0xffffffffu, a, m);
        b += __shfl_xor_sync(0xffffffffu, b, m);
    }
    if (lane == 0) g_lam[h] = expf(a) - expf(b) + LAMBDA_INIT;
}

// ---------------- GEMM: C[M,N] = A[M,K] @ B[N,K]^T (+bias,+res,+gelu) ----------------
template<bool BIAS, bool RES, bool GELU>
__global__ __launch_bounds__(256) void gemm_kernel(const float* __restrict__ A,
                                                   const float* __restrict__ Bm,
                                                   const float* __restrict__ bias,
                                                   const float* __restrict__ res,
                                                   float* __restrict__ C,
                                                   int M, int N, int K) {
    __shared__ float As[16][64];
    __shared__ float Bs[16][64];
    int tid = threadIdx.x;
    int tx = tid & 15, ty = tid >> 4;
    int m0 = blockIdx.y * 64, n0 = blockIdx.x * 64;
    float acc[4][4] = {};
    int lr = tid >> 2;          // 0..63
    int lk = (tid & 3) * 4;     // 0,4,8,12
    const float* Ap = A + (size_t)(m0 + lr) * K + lk;
    const float* Bp = Bm + (size_t)(n0 + lr) * K + lk;
    for (int k0 = 0; k0 < K; k0 += 16) {
        float4 av = *(const float4*)(Ap + k0);
        float4 bv = *(const float4*)(Bp + k0);
        As[lk + 0][lr] = av.x; As[lk + 1][lr] = av.y;
        As[lk + 2][lr] = av.z; As[lk + 3][lr] = av.w;
        Bs[lk + 0][lr] = bv.x; Bs[lk + 1][lr] = bv.y;
        Bs[lk + 2][lr] = bv.z; Bs[lk + 3][lr] = bv.w;
        __syncthreads();
        #pragma unroll
        for (int k = 0; k < 16; k++) {
            float4 a = *(const float4*)&As[k][ty * 4];
            float4 b = *(const float4*)&Bs[k][tx * 4];
            acc[0][0] += a.x * b.x; acc[0][1] += a.x * b.y; acc[0][2] += a.x * b.z; acc[0][3] += a.x * b.w;
            acc[1][0] += a.y * b.x; acc[1][1] += a.y * b.y; acc[1][2] += a.y * b.z; acc[1][3] += a.y * b.w;
            acc[2][0] += a.z * b.x; acc[2][1] += a.z * b.y; acc[2][2] += a.z * b.z; acc[2][3] += a.z * b.w;
            acc[3][0] += a.w * b.x; acc[3][1] += a.w * b.y; acc[3][2] += a.w * b.z; acc[3][3] += a.w * b.w;
        }
        __syncthreads();
    }
    #pragma unroll
    for (int i = 0; i < 4; i++) {
        int m = m0 + ty * 4 + i;
        int n = n0 + tx * 4;
        float4 v;
        v.x = acc[i][0]; v.y = acc[i][1]; v.z = acc[i][2]; v.w = acc[i][3];
        if (BIAS) {
            float4 bb = *(const float4*)(bias + n);
            v.x += bb.x; v.y += bb.y; v.z += bb.z; v.w += bb.w;
        }
        if (GELU) {
            v.x = 0.5f * v.x * (1.0f + erff(v.x * 0.7071067811865476f));
            v.y = 0.5f * v.y * (1.0f + erff(v.y * 0.7071067811865476f));
            v.z = 0.5f * v.z * (1.0f + erff(v.z * 0.7071067811865476f));
            v.w = 0.5f * v.w * (1.0f + erff(v.w * 0.7071067811865476f));
        }
        if (RES) {
            float4 rr = *(const float4*)(res + (size_t)m * N + n);
            v.x += rr.x; v.y += rr.y; v.z += rr.z; v.w += rr.w;
        }
        *(float4*)(C + (size_t)m * N + n) = v;
    }
}

// ---------------- two-stream flash differential attention ----------------
// grid (ND/64, H, B), block 256.  Thread (ty,tx): rows ty*4..+3, key-cols tx*2..+1,
// output cols tx*2..+1.
__global__ __launch_bounds__(256) void attn_kernel(float* __restrict__ out) {
    __shared__ float Q1s[32][64];     // [d][row]
    __shared__ float Q2s[32][64];
    __shared__ float K1s[32][33];     // [key][d]
    __shared__ float K2s[32][33];
    __shared__ float Vs[32][33];      // [key][d]
    __shared__ float P1s[32][65];     // [key][row]
    __shared__ float P2s[32][65];

    int qb = blockIdx.x * 64, h = blockIdx.y, b = blockIdx.z;
    int tid = threadIdx.x;
    int tx = tid & 15, ty = tid >> 4;
    int r0 = ty * 4, c0 = tx * 2;

    const float* Qbase = g_Q + ((size_t)(b * ND) + qb) * (2 * DIM) + h * 64;
    for (int idx = tid; idx < 2048; idx += 256) {
        int d = idx >> 6, r = idx & 63;
        Q1s[d][r] = Qbase[(size_t)r * (2 * DIM) + d];
        Q2s[d][r] = Qbase[(size_t)r * (2 * DIM) + 32 + d];
    }
    float lam = g_lam[h];

    float m1[4], l1[4], m2[4], l2[4];
    float o1[4][2] = {}, o2[4][2] = {};
    #pragma unroll
    for (int i = 0; i < 4; i++) { m1[i] = m2[i] = -1e30f; l1[i] = l2[i] = 0.0f; }

    const float* Kbase = g_K + (size_t)(b * NOC) * (2 * DIM) + h * 64;
    const float* Vbase = g_V + (size_t)(b * NOC) * DIM + h * HD;

    __syncthreads();

    for (int kb = 0; kb < NOC; kb += 32) {
        // cooperative K/V tile load: warp w loads keys w, w+8, w+16, w+24 (coalesced 128B)
        {
            int key = tid >> 5, d = tid & 31;
            #pragma unroll
            for (int kk = key; kk < 32; kk += 8) {
                K1s[kk][d] = Kbase[(size_t)(kb + kk) * (2 * DIM) + d];
                K2s[kk][d] = Kbase[(size_t)(kb + kk) * (2 * DIM) + 32 + d];
                Vs[kk][d]  = Vbase[(size_t)(kb + kk) * DIM + d];
            }
        }
        __syncthreads();

        float s1[4][2] = {}, s2[4][2] = {};
        #pragma unroll
        for (int d = 0; d < 32; d++) {
            float4 q1 = *(const float4*)&Q1s[d][r0];
            float4 q2 = *(const float4*)&Q2s[d][r0];
            float k1a = K1s[c0][d],     k1b = K1s[c0 + 1][d];
            float k2a = K2s[c0][d],     k2b = K2s[c0 + 1][d];
            s1[0][0] += q1.x * k1a; s1[0][1] += q1.x * k1b;
            s1[1][0] += q1.y * k1a; s1[1][1] += q1.y * k1b;
            s1[2][0] += q1.z * k1a; s1[2][1] += q1.z * k1b;
            s1[3][0] += q1.w * k1a; s1[3][1] += q1.w * k1b;
            s2[0][0] += q2.x * k2a; s2[0][1] += q2.x * k2b;
            s2[1][0] += q2.y * k2a; s2[1][1] += q2.y * k2b;
            s2[2][0] += q2.z * k2a; s2[2][1] += q2.z * k2b;
            s2[3][0] += q2.w * k2a; s2[3][1] += q2.w * k2b;
        }

        #pragma unroll
        for (int i = 0; i < 4; i++) {
            // stream 1
            {
                float sa = s1[i][0] * SCALEF, sb = s1[i][1] * SCALEF;
                float tm = fmaxf(sa, sb);
                #pragma unroll
                for (int m = 1; m < 16; m <<= 1)
                    tm = fmaxf(tm, __shfl_xor_sync(0xffffffffu, tm, m));
                float nm = fmaxf(m1[i], tm);
                float corr = __expf(m1[i] - nm);
                float pa = __expf(sa - nm), pb = __expf(sb - nm);
                float ts = pa + pb;
                #pragma unroll
                for (int m = 1; m < 16; m <<= 1)
                    ts += __shfl_xor_sync(0xffffffffu, ts, m);
                l1[i] = l1[i] * corr + ts;
                o1[i][0] *= corr; o1[i][1] *= corr;
                m1[i] = nm;
                P1s[c0][r0 + i] = pa; P1s[c0 + 1][r0 + i] = pb;
            }
            // stream 2
            {
                float sa = s2[i][0] * SCALEF, sb = s2[i][1] * SCALEF;
                float tm = fmaxf(sa, sb);
                #pragma unroll
                for (int m = 1; m < 16; m <<= 1)
                    tm = fmaxf(tm, __shfl_xor_sync(0xffffffffu, tm, m));
                float nm = fmaxf(m2[i], tm);
                float corr = __expf(m2[i] - nm);
                float pa = __expf(sa - nm), pb = __expf(sb - nm);
                float ts = pa + pb;
                #pragma unroll
                for (int m = 1; m < 16; m <<= 1)
                    ts += __shfl_xor_sync(0xffffffffu, ts, m);
                l2[i] = l2[i] * corr + ts;
                o2[i][0] *= corr; o2[i][1] *= corr;
                m2[i] = nm;
                P2s[c0][r0 + i] = pa; P2s[c0 + 1][r0 + i] = pb;
            }
        }
        __syncthreads();

        #pragma unroll 8
        for (int kk = 0; kk < 32; kk++) {
            float va = Vs[kk][c0], vb = Vs[kk][c0 + 1];
            #pragma unroll
            for (int i = 0; i < 4; i++) {
                float p1 = P1s[kk][r0 + i];
                float p2 = P2s[kk][r0 + i];
                o1[i][0] += p1 * va; o1[i][1] += p1 * vb;
                o2[i][0] += p2 * va; o2[i][1] += p2 * vb;
            }
        }
        __syncthreads();
    }

    float* Obase = out + ((size_t)(b * ND) + qb) * DIM + h * HD;
    #pragma unroll
    for (int i = 0; i < 4; i++) {
        float inv1 = 1.0f / l1[i], inv2 = 1.0f / l2[i];
        #pragma unroll
        for (int j = 0; j < 2; j++) {
            float v = o1[i][j] * inv1 - lam * o2[i][j] * inv2;
            Obase[(size_t)(r0 + i) * DIM + c0 + j] = v;
        }
    }
}

// ---------------- ocean passthrough ----------------
__global__ void copy_kernel(const float4* __restrict__ in, float4* __restrict__ out, int n4) {
    int i = blockIdx.x * blockDim.x + threadIdx.x;
    if (i < n4) out[i] = in[i];
}

// ---------------- host ----------------
static float* symaddr(const void* sym) {
    void* p = nullptr;
    cudaGetSymbolAddress(&p, sym);
    return (float*)p;
}

extern "C" void kernel_launch(void* const* d_in, const int* in_sizes, int n_in,
                              void* d_out, int out_size) {
    const float* drift = (const float*)d_in[0];
    const float* ocean = (const float*)d_in[1];
    const float* Wq    = (const float*)d_in[2];
    const float* Wk    = (const float*)d_in[3];
    const float* Wv    = (const float*)d_in[4];
    const float* Wo    = (const float*)d_in[5];
    const float* lq1   = (const float*)d_in[6];
    const float* lk1   = (const float*)d_in[7];
    const float* lq2   = (const float*)d_in[8];
    const float* lk2   = (const float*)d_in[9];
    const float* gamma = (const float*)d_in[10];
    const float* beta  = (const float*)d_in[11];
    const float* fc1w  = (const float*)d_in[12];
    const float* fc1b  = (const float*)d_in[13];
    const float* fc2w  = (const float*)d_in[14];
    const float* fc2b  = (const float*)d_in[15];
    float* out = (float*)d_out;

    float* px    = symaddr(g_x);
    float* pQ    = symaddr(g_Q);
    float* pK    = symaddr(g_K);
    float* pV    = symaddr(g_V);
    float* pAttn = symaddr(g_attn);
    float* pD2   = symaddr(g_d2);
    float* pY    = symaddr(g_y);
    float* pH    = symaddr(g_h);

    // 1. x = LN(drift)
    ln_kernel<<<ROWS / 8, 256>>>(drift, gamma, beta, px);
    // 2. lambda
    lam_kernel<<<1, 256>>>(lq1, lk1, lq2, lk2);
    // 3-5. Q, K, V projections
    gemm_kernel<false, false, false><<<dim3(512 / 64, ROWS / 64), 256>>>(px, Wq, nullptr, nullptr, pQ, ROWS, 512, 256);
    gemm_kernel<false, false, false><<<dim3(512 / 64, ROWS / 64), 256>>>(ocean, Wk, nullptr, nullptr, pK, ROWS, 512, 256);
    gemm_kernel<false, false, false><<<dim3(256 / 64, ROWS / 64), 256>>>(ocean, Wv, nullptr, nullptr, pV, ROWS, 256, 256);
    // 6. differential flash attention
    attn_kernel<<<dim3(ND / 64, NHEAD, BATCH), 256>>>(pAttn);
    // 7. drift2 = drift + attn @ Wo^T
    gemm_kernel<false, true, false><<<dim3(256 / 64, ROWS / 64), 256>>>(pAttn, Wo, nullptr, drift, pD2, ROWS, 256, 256);
    // 8. y = LN(drift2)
    ln_kernel<<<ROWS / 8, 256>>>(pD2, gamma, beta, pY);
    // 9. h = gelu(y @ fc1^T + b1)
    gemm_kernel<true, false, true><<<dim3(1024 / 64, ROWS / 64), 256>>>(pY, fc1w, fc1b, nullptr, pH, ROWS, 1024, 256);
    // 10. out_drift = drift2 + h @ fc2^T + b2   (written straight to d_out)
    gemm_kernel<true, true, false><<<dim3(256 / 64, ROWS / 64), 256>>>(pH, fc2w, fc2b, pD2, out, ROWS, 256, 1024);
    // 11. ocean passthrough
    copy_kernel<<<(ROWS * DIM / 4 + 255) / 256, 256>>>((const float4*)ocean,
                                                       (float4*)(out + (size_t)ROWS * DIM),
                                                       ROWS * DIM / 4);
}

// round 6
// speedup vs baseline: 1.8903x; 1.8903x over previous
#include <cuda_runtime.h>
#include <math.h>

#define DIM 256
#define NHEAD 8
#define HD 32
#define BATCH 2
#define ND 2048
#define NOC 2048
#define ROWS (BATCH*ND)          // 4096
#define EPSF 1e-5f
#define LAMBDA_INIT 0.1f
#define SCALEF 0.17677669529663687f   // 32^-0.5

// ---------------- scratch (static __device__, no allocations) ----------------
__device__ float g_x[ROWS*DIM];        // LN1(drift)
__device__ float g_Q[ROWS*2*DIM];      // x @ Wq^T   [4096,512]
__device__ float g_K[ROWS*2*DIM];      // ocean @ Wk^T
__device__ float g_V[ROWS*DIM];        // ocean @ Wv^T
__device__ float g_attn[ROWS*DIM];     // attention output
__device__ float g_d2[ROWS*DIM];       // drift + attn@Wo^T
__device__ float g_y[ROWS*DIM];        // LN2
__device__ float g_h[ROWS*4*DIM];      // gelu(fc1)
__device__ float g_lam[NHEAD];

// ---------------- tf32 helpers ----------------
__device__ __forceinline__ unsigned f2tf32(float x) {
    unsigned u;
    asm("cvt.rna.tf32.f32 %0, %1;" : "=r"(u) : "f"(x));
    return u;
}

// D(16x8) += A(16x8) * B(8x8), tf32, fp32 accum.
// A row-major frag: a0=(g,t) a1=(g+8,t) a2=(g,t+4) a3=(g+8,t+4)
// B col frag:       b0=(k=t,n=g) b1=(k=t+4,n=g)
// C frag:           c0=(g,2t) c1=(g,2t+1) c2=(g+8,2t) c3=(g+8,2t+1)
__device__ __forceinline__ void mma_tf32(float* c, unsigned a0, unsigned a1,
                                         unsigned a2, unsigned a3,
                                         unsigned b0, unsigned b1) {
    asm volatile(
        "mma.sync.aligned.m16n8k8.row.col.f32.tf32.tf32.f32 "
        "{%0,%1,%2,%3}, {%4,%5,%6,%7}, {%8,%9}, {%0,%1,%2,%3};\n"
        : "+f"(c[0]), "+f"(c[1]), "+f"(c[2]), "+f"(c[3])
        : "r"(a0), "r"(a1), "r"(a2), "r"(a3), "r"(b0), "r"(b1));
}

// ---------------- LayerNorm: one warp per 256-elem row ----------------
__global__ __launch_bounds__(256) void ln_kernel(const float* __restrict__ in,
                                                 const float* __restrict__ gamma,
                                                 const float* __restrict__ beta,
                                                 float* __restrict__ out) {
    int warp = threadIdx.x >> 5, lane = threadIdx.x & 31;
    size_t row = (size_t)blockIdx.x * 8 + warp;
    const float* p = in + row * DIM;
    float4 a = *(const float4*)(p + lane * 4);
    float4 b = *(const float4*)(p + 128 + lane * 4);
    float s  = a.x + a.y + a.z + a.w + b.x + b.y + b.z + b.w;
    float ss = a.x*a.x + a.y*a.y + a.z*a.z + a.w*a.w
             + b.x*b.x + b.y*b.y + b.z*b.z + b.w*b.w;
    #pragma unroll
    for (int m = 16; m; m >>= 1) {
        s  += __shfl_xor_sync(0xffffffffu, s,  m);
        ss += __shfl_xor_sync(0xffffffffu, ss, m);
    }
    float mean = s * (1.0f / DIM);
    float var  = ss * (1.0f / DIM) - mean * mean;
    float rinv = rsqrtf(var + EPSF);
    float4 g1 = *(const float4*)(gamma + lane * 4);
    float4 g2 = *(const float4*)(gamma + 128 + lane * 4);
    float4 b1 = *(const float4*)(beta + lane * 4);
    float4 b2 = *(const float4*)(beta + 128 + lane * 4);
    float4 o1, o2;
    o1.x = (a.x - mean) * rinv * g1.x + b1.x;
    o1.y = (a.y - mean) * rinv * g1.y + b1.y;
    o1.z = (a.z - mean) * rinv * g1.z + b1.z;
    o1.w = (a.w - mean) * rinv * g1.w + b1.w;
    o2.x = (b.x - mean) * rinv * g2.x + b2.x;
    o2.y = (b.y - mean) * rinv * g2.y + b2.y;
    o2.z = (b.z - mean) * rinv * g2.z + b2.z;
    o2.w = (b.w - mean) * rinv * g2.w + b2.w;
    *(float4*)(out + row * DIM + lane * 4) = o1;
    *(float4*)(out + row * DIM + 128 + lane * 4) = o2;
}

// ---------------- lambda per head ----------------
__global__ void lam_kernel(const float* __restrict__ lq1, const float* __restrict__ lk1,
                           const float* __restrict__ lq2, const float* __restrict__ lk2) {
    int h = threadIdx.x >> 5, lane = threadIdx.x & 31;
    float a = lq1[h * HD + lane] * lk1[h * HD + lane];
    float b = lq2[h * HD + lane] * lk2[h * HD + lane];
    #pragma unroll
    for (int m = 16; m; m >>= 1) {
        a += __shfl_xor_sync(0xffffffffu, a, m);
        b += __shfl_xor_sync(0xffffffffu, b, m);
    }
    if (lane == 0) g_lam[h] = expf(a) - expf(b) + LAMBDA_INIT;
}

// ---------------- tensor-core GEMM: C[M,N] = A[M,K] @ B[N,K]^T ----------------
// block tile 128x64, BK=16 double-buffered, 8 warps of 32x32.
// smem stride 20 (== 4 mod 32) -> all fragment LDS patterns conflict-free.
template<bool BIAS, bool RES, bool GELU>
__global__ __launch_bounds__(256) void gemm_tc(const float* __restrict__ A,
                                               const float* __restrict__ Bm,
                                               const float* __restrict__ bias,
                                               const float* __restrict__ res,
                                               float* __restrict__ C,
                                               int M, int N, int K) {
    __shared__ unsigned As[2][128 * 20];
    __shared__ unsigned Bs[2][64 * 20];
    int tid = threadIdx.x;
    int m0 = blockIdx.y * 128, n0 = blockIdx.x * 64;
    int w = tid >> 5, lane = tid & 31;
    int wm = w >> 1, wn = w & 1;
    int grp = lane >> 2, tg = lane & 3;

    float c[2][4][4] = {};

    int lr = tid >> 2;          // 0..63
    int lc = (tid & 3) * 4;     // 0,4,8,12
    const float* Ap = A + (size_t)(m0 + lr) * K + lc;
    const float* Bp = Bm + (size_t)(n0 + lr) * K + lc;

    // preload k-tile 0
    {
        float4 v0 = *(const float4*)(Ap);
        float4 v1 = *(const float4*)(Ap + (size_t)64 * K);
        float4 bv = *(const float4*)(Bp);
        unsigned* d0 = &As[0][lr * 20 + lc];
        d0[0] = f2tf32(v0.x); d0[1] = f2tf32(v0.y); d0[2] = f2tf32(v0.z); d0[3] = f2tf32(v0.w);
        unsigned* d1 = &As[0][(lr + 64) * 20 + lc];
        d1[0] = f2tf32(v1.x); d1[1] = f2tf32(v1.y); d1[2] = f2tf32(v1.z); d1[3] = f2tf32(v1.w);
        unsigned* db = &Bs[0][lr * 20 + lc];
        db[0] = f2tf32(bv.x); db[1] = f2tf32(bv.y); db[2] = f2tf32(bv.z); db[3] = f2tf32(bv.w);
    }
    __syncthreads();

    int nk = K / 16;
    for (int ks = 0; ks < nk; ks++) {
        int buf = ks & 1;
        if (ks + 1 < nk) {
            int k0 = (ks + 1) * 16;
            float4 v0 = *(const float4*)(Ap + k0);
            float4 v1 = *(const float4*)(Ap + (size_t)64 * K + k0);
            float4 bv = *(const float4*)(Bp + k0);
            unsigned* d0 = &As[buf ^ 1][lr * 20 + lc];
            d0[0] = f2tf32(v0.x); d0[1] = f2tf32(v0.y); d0[2] = f2tf32(v0.z); d0[3] = f2tf32(v0.w);
            unsigned* d1 = &As[buf ^ 1][(lr + 64) * 20 + lc];
            d1[0] = f2tf32(v1.x); d1[1] = f2tf32(v1.y); d1[2] = f2tf32(v1.z); d1[3] = f2tf32(v1.w);
            unsigned* db = &Bs[buf ^ 1][lr * 20 + lc];
            db[0] = f2tf32(bv.x); db[1] = f2tf32(bv.y); db[2] = f2tf32(bv.z); db[3] = f2tf32(bv.w);
        }
        #pragma unroll
        for (int k8 = 0; k8 < 16; k8 += 8) {
            unsigned a[2][4];
            #pragma unroll
            for (int mt = 0; mt < 2; mt++) {
                int rb = wm * 32 + mt * 16;
                a[mt][0] = As[buf][(rb + grp) * 20 + k8 + tg];
                a[mt][1] = As[buf][(rb + grp + 8) * 20 + k8 + tg];
                a[mt][2] = As[buf][(rb + grp) * 20 + k8 + tg + 4];
                a[mt][3] = As[buf][(rb + grp + 8) * 20 + k8 + tg + 4];
            }
            #pragma unroll
            for (int nt = 0; nt < 4; nt++) {
                int nb = wn * 32 + nt * 8;
                unsigned b0 = Bs[buf][(nb + grp) * 20 + k8 + tg];
                unsigned b1 = Bs[buf][(nb + grp) * 20 + k8 + tg + 4];
                mma_tf32(c[0][nt], a[0][0], a[0][1], a[0][2], a[0][3], b0, b1);
                mma_tf32(c[1][nt], a[1][0], a[1][1], a[1][2], a[1][3], b0, b1);
            }
        }
        __syncthreads();
    }

    // epilogue
    #pragma unroll
    for (int mt = 0; mt < 2; mt++) {
        #pragma unroll
        for (int nt = 0; nt < 4; nt++) {
            int mrow = m0 + wm * 32 + mt * 16 + grp;
            int ncol = n0 + wn * 32 + nt * 8 + 2 * tg;
            #pragma unroll
            for (int half = 0; half < 2; half++) {
                int r = mrow + half * 8;
                float x0 = c[mt][nt][half * 2 + 0];
                float x1 = c[mt][nt][half * 2 + 1];
                if (BIAS) {
                    const float2 bb = *(const float2*)(bias + ncol);
                    x0 += bb.x; x1 += bb.y;
                }
                if (GELU) {
                    x0 = 0.5f * x0 * (1.0f + erff(x0 * 0.7071067811865476f));
                    x1 = 0.5f * x1 * (1.0f + erff(x1 * 0.7071067811865476f));
                }
                if (RES) {
                    const float2 rr = *(const float2*)(res + (size_t)r * N + ncol);
                    x0 += rr.x; x1 += rr.y;
                }
                float2 v; v.x = x0; v.y = x1;
                *(float2*)(C + (size_t)r * N + ncol) = v;
            }
        }
    }
}

// ---------------- tensor-core two-stream flash differential attention ----------------
// grid (ND/64, H, B), block 256 = 8 warps. warps 0-3: stream1 (16 q-rows each),
// warps 4-7: stream2. 16-key blocks; mma for S and PV; online softmax in c-frag layout.
__global__ __launch_bounds__(256) void attn_tc(float* __restrict__ out) {
    __shared__ unsigned Qs[2][64 * 36];   // [stream][row][d], stride 36
    __shared__ unsigned Ks[2][16 * 36];   // [stream][key][d]
    __shared__ unsigned Vt[32 * 20];      // [d][key], stride 20
    __shared__ unsigned Ps[2][64 * 20];   // [stream][row][key], stride 20

    int qb = blockIdx.x * 64, h = blockIdx.y, b = blockIdx.z;
    int tid = threadIdx.x;
    int w = tid >> 5, lane = tid & 31;
    int s = w >> 2, wq = w & 3;
    int grp = lane >> 2, tg = lane & 3;
    int rb = wq * 16;

    const float* Qbase = g_Q + ((size_t)(b * ND) + qb) * 512 + h * 64;
    for (int idx = tid; idx < 64 * 64; idx += 256) {
        int r = idx >> 6, cc = idx & 63;
        Qs[cc >> 5][r * 36 + (cc & 31)] = f2tf32(Qbase[(size_t)r * 512 + cc]);
    }
    float lam = g_lam[h];

    const float* Kbase = g_K + (size_t)(b * NOC) * 512 + h * 64;
    const float* Vbase = g_V + (size_t)(b * NOC) * 256 + h * 32;

    float mrow[2] = {-1e30f, -1e30f};
    float lrow[2] = {0.0f, 0.0f};
    float o[4][4] = {};   // nt (d-tile), frag

    for (int k0 = 0; k0 < NOC; k0 += 16) {
        __syncthreads();   // prev iter's mma reads of Ks/Vt done
        for (int idx = tid; idx < 16 * 64; idx += 256) {
            int kk = idx >> 6, cc = idx & 63;
            Ks[cc >> 5][kk * 36 + (cc & 31)] = f2tf32(Kbase[(size_t)(k0 + kk) * 512 + cc]);
        }
        for (int idx = tid; idx < 16 * 32; idx += 256) {
            int kk = idx >> 5, d = idx & 31;
            Vt[d * 20 + kk] = f2tf32(Vbase[(size_t)(k0 + kk) * 256 + d]);
        }
        __syncthreads();

        // S = Q K^T  (16 q x 16 keys per warp)
        float sc[2][4] = {};
        #pragma unroll
        for (int kd = 0; kd < 4; kd++) {
            int k8 = kd * 8;
            unsigned a0 = Qs[s][(rb + grp) * 36 + k8 + tg];
            unsigned a1 = Qs[s][(rb + grp + 8) * 36 + k8 + tg];
            unsigned a2 = Qs[s][(rb + grp) * 36 + k8 + tg + 4];
            unsigned a3 = Qs[s][(rb + grp + 8) * 36 + k8 + tg + 4];
            #pragma unroll
            for (int nt = 0; nt < 2; nt++) {
                unsigned b0 = Ks[s][(nt * 8 + grp) * 36 + k8 + tg];
                unsigned b1 = Ks[s][(nt * 8 + grp) * 36 + k8 + tg + 4];
                mma_tf32(sc[nt], a0, a1, a2, a3, b0, b1);
            }
        }
        #pragma unroll
        for (int nt = 0; nt < 2; nt++)
            #pragma unroll
            for (int e = 0; e < 4; e++) sc[nt][e] *= SCALEF;

        // online softmax: row0 = grp (frags 0,1), row1 = grp+8 (frags 2,3)
        float mx0 = fmaxf(fmaxf(sc[0][0], sc[0][1]), fmaxf(sc[1][0], sc[1][1]));
        float mx1 = fmaxf(fmaxf(sc[0][2], sc[0][3]), fmaxf(sc[1][2], sc[1][3]));
        mx0 = fmaxf(mx0, __shfl_xor_sync(0xffffffffu, mx0, 1));
        mx0 = fmaxf(mx0, __shfl_xor_sync(0xffffffffu, mx0, 2));
        mx1 = fmaxf(mx1, __shfl_xor_sync(0xffffffffu, mx1, 1));
        mx1 = fmaxf(mx1, __shfl_xor_sync(0xffffffffu, mx1, 2));
        float nm0 = fmaxf(mrow[0], mx0), nm1 = fmaxf(mrow[1], mx1);
        float cr0 = __expf(mrow[0] - nm0), cr1 = __expf(mrow[1] - nm1);
        mrow[0] = nm0; mrow[1] = nm1;
        float p[2][4];
        #pragma unroll
        for (int nt = 0; nt < 2; nt++) {
            p[nt][0] = __expf(sc[nt][0] - nm0);
            p[nt][1] = __expf(sc[nt][1] - nm0);
            p[nt][2] = __expf(sc[nt][2] - nm1);
            p[nt][3] = __expf(sc[nt][3] - nm1);
        }
        float ts0 = p[0][0] + p[0][1] + p[1][0] + p[1][1];
        float ts1 = p[0][2] + p[0][3] + p[1][2] + p[1][3];
        ts0 += __shfl_xor_sync(0xffffffffu, ts0, 1);
        ts0 += __shfl_xor_sync(0xffffffffu, ts0, 2);
        ts1 += __shfl_xor_sync(0xffffffffu, ts1, 1);
        ts1 += __shfl_xor_sync(0xffffffffu, ts1, 2);
        lrow[0] = lrow[0] * cr0 + ts0;
        lrow[1] = lrow[1] * cr1 + ts1;
        #pragma unroll
        for (int nt = 0; nt < 4; nt++) {
            o[nt][0] *= cr0; o[nt][1] *= cr0;
            o[nt][2] *= cr1; o[nt][3] *= cr1;
        }
        // stage P (warp-local rows)
        #pragma unroll
        for (int nt = 0; nt < 2; nt++) {
            int col = nt * 8 + 2 * tg;
            Ps[s][(rb + grp) * 20 + col]     = f2tf32(p[nt][0]);
            Ps[s][(rb + grp) * 20 + col + 1] = f2tf32(p[nt][1]);
            Ps[s][(rb + grp + 8) * 20 + col]     = f2tf32(p[nt][2]);
            Ps[s][(rb + grp + 8) * 20 + col + 1] = f2tf32(p[nt][3]);
        }
        __syncwarp();

        // O += P V  (16 q x 32 d per warp)
        #pragma unroll
        for (int kk8 = 0; kk8 < 16; kk8 += 8) {
            unsigned a0 = Ps[s][(rb + grp) * 20 + kk8 + tg];
            unsigned a1 = Ps[s][(rb + grp + 8) * 20 + kk8 + tg];
            unsigned a2 = Ps[s][(rb + grp) * 20 + kk8 + tg + 4];
            unsigned a3 = Ps[s][(rb + grp + 8) * 20 + kk8 + tg + 4];
            #pragma unroll
            for (int nt = 0; nt < 4; nt++) {
                unsigned b0 = Vt[(nt * 8 + grp) * 20 + kk8 + tg];
                unsigned b1 = Vt[(nt * 8 + grp) * 20 + kk8 + tg + 4];
                mma_tf32(o[nt], a0, a1, a2, a3, b0, b1);
            }
        }
    }

    // combine: out = O1/l1 - lam*O2/l2  (stream2 -> smem, stream1 reads)
    float inv0 = 1.0f / lrow[0], inv1 = 1.0f / lrow[1];
    __syncthreads();
    float* Osm = (float*)&Qs[0][0];   // 64 x 32, stride 36 (Qs dead now)
    if (s == 1) {
        #pragma unroll
        for (int nt = 0; nt < 4; nt++) {
            int col = nt * 8 + 2 * tg;
            Osm[(rb + grp) * 36 + col]     = o[nt][0] * inv0 * lam;
            Osm[(rb + grp) * 36 + col + 1] = o[nt][1] * inv0 * lam;
            Osm[(rb + grp + 8) * 36 + col]     = o[nt][2] * inv1 * lam;
            Osm[(rb + grp + 8) * 36 + col + 1] = o[nt][3] * inv1 * lam;
        }
    }
    __syncthreads();
    if (s == 0) {
        float* Obase = out + ((size_t)(b * ND) + qb) * 256 + h * 32;
        #pragma unroll
        for (int nt = 0; nt < 4; nt++) {
            int col = nt * 8 + 2 * tg;
            float2 v0, v1;
            v0.x = o[nt][0] * inv0 - Osm[(rb + grp) * 36 + col];
            v0.y = o[nt][1] * inv0 - Osm[(rb + grp) * 36 + col + 1];
            v1.x = o[nt][2] * inv1 - Osm[(rb + grp + 8) * 36 + col];
            v1.y = o[nt][3] * inv1 - Osm[(rb + grp + 8) * 36 + col + 1];
            *(float2*)(Obase + (size_t)(rb + grp) * 256 + col) = v0;
            *(float2*)(Obase + (size_t)(rb + grp + 8) * 256 + col) = v1;
        }
    }
}

// ---------------- ocean passthrough ----------------
__global__ void copy_kernel(const float4* __restrict__ in, float4* __restrict__ out, int n4) {
    int i = blockIdx.x * blockDim.x + threadIdx.x;
    if (i < n4) out[i] = in[i];
}

// ---------------- host ----------------
static float* symaddr(const void* sym) {
    void* p = nullptr;
    cudaGetSymbolAddress(&p, sym);
    return (float*)p;
}

extern "C" void kernel_launch(void* const* d_in, const int* in_sizes, int n_in,
                              void* d_out, int out_size) {
    const float* drift = (const float*)d_in[0];
    const float* ocean = (const float*)d_in[1];
    const float* Wq    = (const float*)d_in[2];
    const float* Wk    = (const float*)d_in[3];
    const float* Wv    = (const float*)d_in[4];
    const float* Wo    = (const float*)d_in[5];
    const float* lq1   = (const float*)d_in[6];
    const float* lk1   = (const float*)d_in[7];
    const float* lq2   = (const float*)d_in[8];
    const float* lk2   = (const float*)d_in[9];
    const float* gamma = (const float*)d_in[10];
    const float* beta  = (const float*)d_in[11];
    const float* fc1w  = (const float*)d_in[12];
    const float* fc1b  = (const float*)d_in[13];
    const float* fc2w  = (const float*)d_in[14];
    const float* fc2b  = (const float*)d_in[15];
    float* out = (float*)d_out;

    float* px    = symaddr(g_x);
    float* pQ    = symaddr(g_Q);
    float* pK    = symaddr(g_K);
    float* pV    = symaddr(g_V);
    float* pAttn = symaddr(g_attn);
    float* pD2   = symaddr(g_d2);
    float* pY    = symaddr(g_y);
    float* pH    = symaddr(g_h);

    // 1. x = LN(drift)
    ln_kernel<<<ROWS / 8, 256>>>(drift, gamma, beta, px);
    // 2. lambda
    lam_kernel<<<1, 256>>>(lq1, lk1, lq2, lk2);
    // 3-5. Q, K, V projections (tf32 tensor cores)
    gemm_tc<false, false, false><<<dim3(512 / 64, ROWS / 128), 256>>>(px, Wq, nullptr, nullptr, pQ, ROWS, 512, 256);
    gemm_tc<false, false, false><<<dim3(512 / 64, ROWS / 128), 256>>>(ocean, Wk, nullptr, nullptr, pK, ROWS, 512, 256);
    gemm_tc<false, false, false><<<dim3(256 / 64, ROWS / 128), 256>>>(ocean, Wv, nullptr, nullptr, pV, ROWS, 256, 256);
    // 6. differential flash attention (tf32 tensor cores)
    attn_tc<<<dim3(ND / 64, NHEAD, BATCH), 256>>>(pAttn);
    // 7. drift2 = drift + attn @ Wo^T
    gemm_tc<false, true, false><<<dim3(256 / 64, ROWS / 128), 256>>>(pAttn, Wo, nullptr, drift, pD2, ROWS, 256, 256);
    // 8. y = LN(drift2)
    ln_kernel<<<ROWS / 8, 256>>>(pD2, gamma, beta, pY);
    // 9. h = gelu(y @ fc1^T + b1)
    gemm_tc<true, false, true><<<dim3(1024 / 64, ROWS / 128), 256>>>(pY, fc1w, fc1b, nullptr, pH, ROWS, 1024, 256);
    // 10. out_drift = drift2 + h @ fc2^T + b2
    gemm_tc<true, true, false><<<dim3(256 / 64, ROWS / 128), 256>>>(pH, fc2w, fc2b, pD2, out, ROWS, 256, 1024);
    // 11. ocean passthrough
    copy_kernel<<<(ROWS * DIM / 4 + 255) / 256, 256>>>((const float4*)ocean,
                                                       (float4*)(out + (size_t)ROWS * DIM),
                                                       ROWS * DIM / 4);
}

// round 14
// speedup vs baseline: 2.3369x; 1.2363x over previous
#include <cuda_runtime.h>
#include <math.h>

#define DIM 256
#define NHEAD 8
#define HD 32
#define BATCH 2
#define ND 2048
#define NOC 2048
#define ROWS (BATCH*ND)          // 4096
#define EPSF 1e-5f
#define LAMBDA_INIT 0.1f
#define SCALEF 0.17677669529663687f   // 32^-0.5

// ---------------- scratch (static __device__, no allocations) ----------------
__device__ float g_x[ROWS*DIM];        // LN1(drift)
__device__ float g_Q[ROWS*2*DIM];      // x @ Wq^T   [4096,512]
__device__ float g_K[ROWS*2*DIM];      // ocean @ Wk^T
__device__ float g_V[ROWS*DIM];        // ocean @ Wv^T
__device__ float g_attn[ROWS*DIM];     // attention output
__device__ float g_d2[ROWS*DIM];       // drift + attn@Wo^T
__device__ float g_y[ROWS*DIM];        // LN2
__device__ float g_h[ROWS*4*DIM];      // gelu(fc1)
__device__ float g_lam[NHEAD];

// ---------------- tf32 helpers ----------------
__device__ __forceinline__ unsigned f2tf32(float x) {
    unsigned u;
    asm("cvt.rna.tf32.f32 %0, %1;" : "=r"(u) : "f"(x));
    return u;
}

// D(16x8) += A(16x8) * B(8x8), tf32, fp32 accum.
__device__ __forceinline__ void mma_tf32(float* c, unsigned a0, unsigned a1,
                                         unsigned a2, unsigned a3,
                                         unsigned b0, unsigned b1) {
    asm volatile(
        "mma.sync.aligned.m16n8k8.row.col.f32.tf32.tf32.f32 "
        "{%0,%1,%2,%3}, {%4,%5,%6,%7}, {%8,%9}, {%0,%1,%2,%3};\n"
        : "+f"(c[0]), "+f"(c[1]), "+f"(c[2]), "+f"(c[3])
        : "r"(a0), "r"(a1), "r"(a2), "r"(a3), "r"(b0), "r"(b1));
}

// ---------------- LayerNorm: one warp per 256-elem row ----------------
__global__ __launch_bounds__(256) void ln_kernel(const float* __restrict__ in,
                                                 const float* __restrict__ gamma,
                                                 const float* __restrict__ beta,
                                                 float* __restrict__ out) {
    int warp = threadIdx.x >> 5, lane = threadIdx.x & 31;
    size_t row = (size_t)blockIdx.x * 8 + warp;
    const float* p = in + row * DIM;
    float4 a = *(const float4*)(p + lane * 4);
    float4 b = *(const float4*)(p + 128 + lane * 4);
    float s  = a.x + a.y + a.z + a.w + b.x + b.y + b.z + b.w;
    float ss = a.x*a.x + a.y*a.y + a.z*a.z + a.w*a.w
             + b.x*b.x + b.y*b.y + b.z*b.z + b.w*b.w;
    #pragma unroll
    for (int m = 16; m; m >>= 1) {
        s  += __shfl_xor_sync(0xffffffffu, s,  m);
        ss += __shfl_xor_sync(0xffffffffu, ss, m);
    }
    float mean = s * (1.0f / DIM);
    float var  = ss * (1.0f / DIM) - mean * mean;
    float rinv = rsqrtf(var + EPSF);
    float4 g1 = *(const float4*)(gamma + lane * 4);
    float4 g2 = *(const float4*)(gamma + 128 + lane * 4);
    float4 b1 = *(const float4*)(beta + lane * 4);
    float4 b2 = *(const float4*)(beta + 128 + lane * 4);
    float4 o1, o2;
    o1.x = (a.x - mean) * rinv * g1.x + b1.x;
    o1.y = (a.y - mean) * rinv * g1.y + b1.y;
    o1.z = (a.z - mean) * rinv * g1.z + b1.z;
    o1.w = (a.w - mean) * rinv * g1.w + b1.w;
    o2.x = (b.x - mean) * rinv * g2.x + b2.x;
    o2.y = (b.y - mean) * rinv * g2.y + b2.y;
    o2.z = (b.z - mean) * rinv * g2.z + b2.z;
    o2.w = (b.w - mean) * rinv * g2.w + b2.w;
    *(float4*)(out + row * DIM + lane * 4) = o1;
    *(float4*)(out + row * DIM + 128 + lane * 4) = o2;
}

// ---------------- lambda per head ----------------
__global__ void lam_kernel(const float* __restrict__ lq1, const float* __restrict__ lk1,
                           const float* __restrict__ lq2, const float* __restrict__ lk2) {
    int h = threadIdx.x >> 5, lane = threadIdx.x & 31;
    float a = lq1[h * HD + lane] * lk1[h * HD + lane];
    float b = lq2[h * HD + lane] * lk2[h * HD + lane];
    #pragma unroll
    for (int m = 16; m; m >>= 1) {
        a += __shfl_xor_sync(0xffffffffu, a, m);
        b += __shfl_xor_sync(0xffffffffu, b, m);
    }
    if (lane == 0) g_lam[h] = expf(a) - expf(b) + LAMBDA_INIT;
}

// ---------------- tensor-core GEMM v2: C[M,N] = A[M,K] @ B[N,K]^T ----------------
// 64x64 block tile (was 128x64) for 2x grid / higher occupancy. 256 threads,
// 8 warps each 16x32 (1 m16 tile x 4 n8 tiles). BK=16 double-buffered,
// smem stride 20 -> conflict-free fragment loads.
template<bool BIAS, bool RES, bool GELU>
__global__ __launch_bounds__(256) void gemm_tc(const float* __restrict__ A,
                                               const float* __restrict__ Bm,
                                               const float* __restrict__ bias,
                                               const float* __restrict__ res,
                                               float* __restrict__ C,
                                               int M, int N, int K) {
    __shared__ unsigned As[2][64 * 20];
    __shared__ unsigned Bs[2][64 * 20];
    int tid = threadIdx.x;
    int m0 = blockIdx.y * 64, n0 = blockIdx.x * 64;
    int w = tid >> 5, lane = tid & 31;
    int wm = w >> 1, wn = w & 1;            // wm in [0,4): 16-row slab; wn in [0,2): 32-col slab
    int grp = lane >> 2, tg = lane & 3;

    float c[4][4] = {};

    int lr = tid >> 2;          // 0..63
    int lc = (tid & 3) * 4;     // 0,4,8,12
    const float* Ap = A + (size_t)(m0 + lr) * K + lc;
    const float* Bp = Bm + (size_t)(n0 + lr) * K + lc;

    // preload k-tile 0
    {
        float4 av = *(const float4*)(Ap);
        float4 bv = *(const float4*)(Bp);
        unsigned* da = &As[0][lr * 20 + lc];
        da[0] = f2tf32(av.x); da[1] = f2tf32(av.y); da[2] = f2tf32(av.z); da[3] = f2tf32(av.w);
        unsigned* db = &Bs[0][lr * 20 + lc];
        db[0] = f2tf32(bv.x); db[1] = f2tf32(bv.y); db[2] = f2tf32(bv.z); db[3] = f2tf32(bv.w);
    }
    __syncthreads();

    int nk = K / 16;
    for (int ks = 0; ks < nk; ks++) {
        int buf = ks & 1;
        if (ks + 1 < nk) {
            int k0 = (ks + 1) * 16;
            float4 av = *(const float4*)(Ap + k0);
            float4 bv = *(const float4*)(Bp + k0);
            unsigned* da = &As[buf ^ 1][lr * 20 + lc];
            da[0] = f2tf32(av.x); da[1] = f2tf32(av.y); da[2] = f2tf32(av.z); da[3] = f2tf32(av.w);
            unsigned* db = &Bs[buf ^ 1][lr * 20 + lc];
            db[0] = f2tf32(bv.x); db[1] = f2tf32(bv.y); db[2] = f2tf32(bv.z); db[3] = f2tf32(bv.w);
        }
        #pragma unroll
        for (int k8 = 0; k8 < 16; k8 += 8) {
            int rb = wm * 16;
            unsigned a0 = As[buf][(rb + grp) * 20 + k8 + tg];
            unsigned a1 = As[buf][(rb + grp + 8) * 20 + k8 + tg];
            unsigned a2 = As[buf][(rb + grp) * 20 + k8 + tg + 4];
            unsigned a3 = As[buf][(rb + grp + 8) * 20 + k8 + tg + 4];
            #pragma unroll
            for (int nt = 0; nt < 4; nt++) {
                int nb = wn * 32 + nt * 8;
                unsigned b0 = Bs[buf][(nb + grp) * 20 + k8 + tg];
                unsigned b1 = Bs[buf][(nb + grp) * 20 + k8 + tg + 4];
                mma_tf32(c[nt], a0, a1, a2, a3, b0, b1);
            }
        }
        __syncthreads();
    }

    // epilogue
    #pragma unroll
    for (int nt = 0; nt < 4; nt++) {
        int mrow = m0 + wm * 16 + grp;
        int ncol = n0 + wn * 32 + nt * 8 + 2 * tg;
        #pragma unroll
        for (int half = 0; half < 2; half++) {
            int r = mrow + half * 8;
            float x0 = c[nt][half * 2 + 0];
            float x1 = c[nt][half * 2 + 1];
            if (BIAS) {
                const float2 bb = *(const float2*)(bias + ncol);
                x0 += bb.x; x1 += bb.y;
            }
            if (GELU) {
                x0 = 0.5f * x0 * (1.0f + erff(x0 * 0.7071067811865476f));
                x1 = 0.5f * x1 * (1.0f + erff(x1 * 0.7071067811865476f));
            }
            if (RES) {
                const float2 rr = *(const float2*)(res + (size_t)r * N + ncol);
                x0 += rr.x; x1 += rr.y;
            }
            float2 v; v.x = x0; v.y = x1;
            *(float2*)(C + (size_t)r * N + ncol) = v;
        }
    }
}

// ---------------- tensor-core two-stream flash differential attention v2 ----------------
// grid (ND/64, H, B), block 256 = 8 warps. warps 0-3: stream1, warps 4-7: stream2.
// 32-key tiles (64 iters), Q fragments in registers (pre-scaled by SCALEF),
// register-prefetch software pipeline for K/V.
__global__ __launch_bounds__(256) void attn_tc(float* __restrict__ out) {
    __shared__ unsigned Ks[2][32 * 36];   // [stream][key][d]  stride 36
    __shared__ unsigned Vt[32 * 36];      // [d][key]          stride 36
    __shared__ unsigned Ps[2][64 * 36];   // [stream][row][key] stride 36 (also Q staging / combine staging)

    int qb = blockIdx.x * 64, h = blockIdx.y, b = blockIdx.z;
    int tid = threadIdx.x;
    int w = tid >> 5, lane = tid & 31;
    int s = w >> 2, wq = w & 3;
    int grp = lane >> 2, tg = lane & 3;
    int rb = wq * 16;

    float lam = g_lam[h];
    const float* Qbase = g_Q + ((size_t)(b * ND) + qb) * 512 + h * 64;
    const float* Kbase = g_K + (size_t)(b * NOC) * 512 + h * 64;
    const float* Vbase = g_V + (size_t)(b * NOC) * 256 + h * 32;

    // ---- stage Q (scaled) into Ps, then hoist fragments to registers ----
    for (int idx = tid; idx < 64 * 64; idx += 256) {
        int r = idx >> 6, cc = idx & 63;
        Ps[cc >> 5][r * 36 + (cc & 31)] = f2tf32(SCALEF * Qbase[(size_t)r * 512 + cc]);
    }
    __syncthreads();
    unsigned qa[4][4];
    #pragma unroll
    for (int kd = 0; kd < 4; kd++) {
        int k8 = kd * 8;
        qa[kd][0] = Ps[s][(rb + grp) * 36 + k8 + tg];
        qa[kd][1] = Ps[s][(rb + grp + 8) * 36 + k8 + tg];
        qa[kd][2] = Ps[s][(rb + grp) * 36 + k8 + tg + 4];
        qa[kd][3] = Ps[s][(rb + grp + 8) * 36 + k8 + tg + 4];
    }

    // ---- prefetch tile 0 into registers ----
    float rK[8], rV[4];
    #pragma unroll
    for (int i = 0; i < 8; i++) {
        int idx = tid + i * 256;             // 32 keys x 64 cols
        int kk = idx >> 6, cc = idx & 63;
        rK[i] = Kbase[(size_t)kk * 512 + cc];
    }
    #pragma unroll
    for (int i = 0; i < 4; i++) {
        int idx = tid + i * 256;             // 32 keys x 32 d
        int kk = idx >> 5, d = idx & 31;
        rV[i] = Vbase[(size_t)kk * 256 + d];
    }
    __syncthreads();   // Q fragment extraction complete before Ps reused
    // store tile 0
    #pragma unroll
    for (int i = 0; i < 8; i++) {
        int idx = tid + i * 256;
        int kk = idx >> 6, cc = idx & 63;
        Ks[cc >> 5][kk * 36 + (cc & 31)] = f2tf32(rK[i]);
    }
    #pragma unroll
    for (int i = 0; i < 4; i++) {
        int idx = tid + i * 256;
        int kk = idx >> 5, d = idx & 31;
        Vt[d * 36 + kk] = f2tf32(rV[i]);
    }
    __syncthreads();

    float mrow[2] = {-1e30f, -1e30f};
    float lrow[2] = {0.0f, 0.0f};
    float o[4][4] = {};

    for (int t = 0; t < 64; t++) {
        // issue prefetch for next tile (latency hidden by compute below)
        if (t < 63) {
            const float* Kb = Kbase + (size_t)(t + 1) * 32 * 512;
            const float* Vb = Vbase + (size_t)(t + 1) * 32 * 256;
            #pragma unroll
            for (int i = 0; i < 8; i++) {
                int idx = tid + i * 256;
                int kk = idx >> 6, cc = idx & 63;
                rK[i] = Kb[(size_t)kk * 512 + cc];
            }
            #pragma unroll
            for (int i = 0; i < 4; i++) {
                int idx = tid + i * 256;
                int kk = idx >> 5, d = idx & 31;
                rV[i] = Vb[(size_t)kk * 256 + d];
            }
        }

        // ---- S = Q K^T  (16 q x 32 keys per warp) ----
        float sc[4][4] = {};
        #pragma unroll
        for (int kd = 0; kd < 4; kd++) {
            int k8 = kd * 8;
            #pragma unroll
            for (int nt = 0; nt < 4; nt++) {
                unsigned b0 = Ks[s][(nt * 8 + grp) * 36 + k8 + tg];
                unsigned b1 = Ks[s][(nt * 8 + grp) * 36 + k8 + tg + 4];
                mma_tf32(sc[nt], qa[kd][0], qa[kd][1], qa[kd][2], qa[kd][3], b0, b1);
            }
        }

        // ---- online softmax ----
        float mx0 = fmaxf(fmaxf(sc[0][0], sc[0][1]), fmaxf(sc[1][0], sc[1][1]));
        mx0 = fmaxf(mx0, fmaxf(fmaxf(sc[2][0], sc[2][1]), fmaxf(sc[3][0], sc[3][1])));
        float mx1 = fmaxf(fmaxf(sc[0][2], sc[0][3]), fmaxf(sc[1][2], sc[1][3]));
        mx1 = fmaxf(mx1, fmaxf(fmaxf(sc[2][2], sc[2][3]), fmaxf(sc[3][2], sc[3][3])));
        mx0 = fmaxf(mx0, __shfl_xor_sync(0xffffffffu, mx0, 1));
        mx0 = fmaxf(mx0, __shfl_xor_sync(0xffffffffu, mx0, 2));
        mx1 = fmaxf(mx1, __shfl_xor_sync(0xffffffffu, mx1, 1));
        mx1 = fmaxf(mx1, __shfl_xor_sync(0xffffffffu, mx1, 2));
        float nm0 = fmaxf(mrow[0], mx0), nm1 = fmaxf(mrow[1], mx1);
        float cr0 = __expf(mrow[0] - nm0), cr1 = __expf(mrow[1] - nm1);
        mrow[0] = nm0; mrow[1] = nm1;
        float p[4][4];
        #pragma unroll
        for (int nt = 0; nt < 4; nt++) {
            p[nt][0] = __expf(sc[nt][0] - nm0);
            p[nt][1] = __expf(sc[nt][1] - nm0);
            p[nt][2] = __expf(sc[nt][2] - nm1);
            p[nt][3] = __expf(sc[nt][3] - nm1);
        }
        float ts0 = (p[0][0] + p[0][1]) + (p[1][0] + p[1][1])
                  + (p[2][0] + p[2][1]) + (p[3][0] + p[3][1]);
        float ts1 = (p[0][2] + p[0][3]) + (p[1][2] + p[1][3])
                  + (p[2][2] + p[2][3]) + (p[3][2] + p[3][3]);
        ts0 += __shfl_xor_sync(0xffffffffu, ts0, 1);
        ts0 += __shfl_xor_sync(0xffffffffu, ts0, 2);
        ts1 += __shfl_xor_sync(0xffffffffu, ts1, 1);
        ts1 += __shfl_xor_sync(0xffffffffu, ts1, 2);
        lrow[0] = lrow[0] * cr0 + ts0;
        lrow[1] = lrow[1] * cr1 + ts1;
        #pragma unroll
        for (int nt = 0; nt < 4; nt++) {
            o[nt][0] *= cr0; o[nt][1] *= cr0;
            o[nt][2] *= cr1; o[nt][3] *= cr1;
        }

        // ---- stage P (warp-local rows) ----
        #pragma unroll
        for (int nt = 0; nt < 4; nt++) {
            int col = nt * 8 + 2 * tg;
            Ps[s][(rb + grp) * 36 + col]         = f2tf32(p[nt][0]);
            Ps[s][(rb + grp) * 36 + col + 1]     = f2tf32(p[nt][1]);
            Ps[s][(rb + grp + 8) * 36 + col]     = f2tf32(p[nt][2]);
            Ps[s][(rb + grp + 8) * 36 + col + 1] = f2tf32(p[nt][3]);
        }
        __syncwarp();

        // ---- O += P V  (16 q x 32 d per warp, k=32 keys) ----
        #pragma unroll
        for (int kk8 = 0; kk8 < 32; kk8 += 8) {
            unsigned a0 = Ps[s][(rb + grp) * 36 + kk8 + tg];
            unsigned a1 = Ps[s][(rb + grp + 8) * 36 + kk8 + tg];
            unsigned a2 = Ps[s][(rb + grp) * 36 + kk8 + tg + 4];
            unsigned a3 = Ps[s][(rb + grp + 8) * 36 + kk8 + tg + 4];
            #pragma unroll
            for (int nt = 0; nt < 4; nt++) {
                unsigned b0 = Vt[(nt * 8 + grp) * 36 + kk8 + tg];
                unsigned b1 = Vt[(nt * 8 + grp) * 36 + kk8 + tg + 4];
                mma_tf32(o[nt], a0, a1, a2, a3, b0, b1);
            }
        }
        __syncthreads();   // all smem reads of this tile complete

        if (t < 63) {
            #pragma unroll
            for (int i = 0; i < 8; i++) {
                int idx = tid + i * 256;
                int kk = idx >> 6, cc = idx & 63;
                Ks[cc >> 5][kk * 36 + (cc & 31)] = f2tf32(rK[i]);
            }
            #pragma unroll
            for (int i = 0; i < 4; i++) {
                int idx = tid + i * 256;
                int kk = idx >> 5, d = idx & 31;
                Vt[d * 36 + kk] = f2tf32(rV[i]);
            }
            __syncthreads();   // new tile visible
        }
    }

    // ---- combine: out = O1/l1 - lam*O2/l2  (stream2 -> Ps[0], stream1 reads) ----
    float inv0 = 1.0f / lrow[0], inv1 = 1.0f / lrow[1];
    float* Osm = (float*)&Ps[0][0];   // 64 x 32, stride 36
    if (s == 1) {
        #pragma unroll
        for (int nt = 0; nt < 4; nt++) {
            int col = nt * 8 + 2 * tg;
            Osm[(rb + grp) * 36 + col]         = o[nt][0] * inv0 * lam;
            Osm[(rb + grp) * 36 + col + 1]     = o[nt][1] * inv0 * lam;
            Osm[(rb + grp + 8) * 36 + col]     = o[nt][2] * inv1 * lam;
            Osm[(rb + grp + 8) * 36 + col + 1] = o[nt][3] * inv1 * lam;
        }
    }
    __syncthreads();
    if (s == 0) {
        float* Obase = out + ((size_t)(b * ND) + qb) * 256 + h * 32;
        #pragma unroll
        for (int nt = 0; nt < 4; nt++) {
            int col = nt * 8 + 2 * tg;
            float2 v0, v1;
            v0.x = o[nt][0] * inv0 - Osm[(rb + grp) * 36 + col];
            v0.y = o[nt][1] * inv0 - Osm[(rb + grp) * 36 + col + 1];
            v1.x = o[nt][2] * inv1 - Osm[(rb + grp + 8) * 36 + col];
            v1.y = o[nt][3] * inv1 - Osm[(rb + grp + 8) * 36 + col + 1];
            *(float2*)(Obase + (size_t)(rb + grp) * 256 + col) = v0;
            *(float2*)(Obase + (size_t)(rb + grp + 8) * 256 + col) = v1;
        }
    }
}

// ---------------- ocean passthrough ----------------
__global__ void copy_kernel(const float4* __restrict__ in, float4* __restrict__ out, int n4) {
    int i = blockIdx.x * blockDim.x + threadIdx.x;
    if (i < n4) out[i] = in[i];
}

// ---------------- host ----------------
static float* symaddr(const void* sym) {
    void* p = nullptr;
    cudaGetSymbolAddress(&p, sym);
    return (float*)p;
}

extern "C" void kernel_launch(void* const* d_in, const int* in_sizes, int n_in,
                              void* d_out, int out_size) {
    const float* drift = (const float*)d_in[0];
    const float* ocean = (const float*)d_in[1];
    const float* Wq    = (const float*)d_in[2];
    const float* Wk    = (const float*)d_in[3];
    const float* Wv    = (const float*)d_in[4];
    const float* Wo    = (const float*)d_in[5];
    const float* lq1   = (const float*)d_in[6];
    const float* lk1   = (const float*)d_in[7];
    const float* lq2   = (const float*)d_in[8];
    const float* lk2   = (const float*)d_in[9];
    const float* gamma = (const float*)d_in[10];
    const float* beta  = (const float*)d_in[11];
    const float* fc1w  = (const float*)d_in[12];
    const float* fc1b  = (const float*)d_in[13];
    const float* fc2w  = (const float*)d_in[14];
    const float* fc2b  = (const float*)d_in[15];
    float* out = (float*)d_out;

    float* px    = symaddr(g_x);
    float* pQ    = symaddr(g_Q);
    float* pK    = symaddr(g_K);
    float* pV    = symaddr(g_V);
    float* pAttn = symaddr(g_attn);
    float* pD2   = symaddr(g_d2);
    float* pY    = symaddr(g_y);
    float* pH    = symaddr(g_h);

    // 1. x = LN(drift)
    ln_kernel<<<ROWS / 8, 256>>>(drift, gamma, beta, px);
    // 2. lambda
    lam_kernel<<<1, 256>>>(lq1, lk1, lq2, lk2);
    // 3-5. Q, K, V projections (tf32 tensor cores, 64x64 tiles)
    gemm_tc<false, false, false><<<dim3(512 / 64, ROWS / 64), 256>>>(px, Wq, nullptr, nullptr, pQ, ROWS, 512, 256);
    gemm_tc<false, false, false><<<dim3(512 / 64, ROWS / 64), 256>>>(ocean, Wk, nullptr, nullptr, pK, ROWS, 512, 256);
    gemm_tc<false, false, false><<<dim3(256 / 64, ROWS / 64), 256>>>(ocean, Wv, nullptr, nullptr, pV, ROWS, 256, 256);
    // 6. differential flash attention (tf32 tensor cores, v2)
    attn_tc<<<dim3(ND / 64, NHEAD, BATCH), 256>>>(pAttn);
    // 7. drift2 = drift + attn @ Wo^T
    gemm_tc<false, true, false><<<dim3(256 / 64, ROWS / 64), 256>>>(pAttn, Wo, nullptr, drift, pD2, ROWS, 256, 256);
    // 8. y = LN(drift2)
    ln_kernel<<<ROWS / 8, 256>>>(pD2, gamma, beta, pY);
    // 9. h = gelu(y @ fc1^T + b1)
    gemm_tc<true, false, true><<<dim3(1024 / 64, ROWS / 64), 256>>>(pY, fc1w, fc1b, nullptr, pH, ROWS, 1024, 256);
    // 10. out_drift = drift2 + h @ fc2^T + b2
    gemm_tc<true, true, false><<<dim3(256 / 64, ROWS / 64), 256>>>(pH, fc2w, fc2b, pD2, out, ROWS, 256, 1024);
    // 11. ocean passthrough
    copy_kernel<<<(ROWS * DIM / 4 + 255) / 256, 256>>>((const float4*)ocean,
                                                       (float4*)(out + (size_t)ROWS * DIM),
                                                       ROWS * DIM / 4);
}